// round 10
// baseline (speedup 1.0000x reference)
#include <cuda_runtime.h>
#include <cuda_bf16.h>
#include <cstdint>

#define MAXN 50000
#define DD 128
#define MAXE 800000
#define LL 4
#define SCAN_B 1024

// Scratch (no allocations allowed)
__device__ int    g_deg[MAXN];
__device__ int    g_fill[MAXN];
__device__ int    g_rowptr[MAXN + 1];
__device__ int    g_bsum[64];
__device__ int    g_boff[64];
__device__ int    g_csr_src[MAXE];
__device__ float  g_dinv[MAXN];
__device__ float  g_h[(size_t)MAXN * DD];    // h' = (X@W)*dinv[row]
__device__ float  g_buf[(size_t)MAXN * DD];  // layer output ping buffer

// ---------------- preprocessing ----------------

__global__ void zero_counters_kernel(int n) {
    int i = blockIdx.x * blockDim.x + threadIdx.x;
    if (i < n) { g_deg[i] = 0; g_fill[i] = 0; }
}

__global__ void count_deg_kernel(const int* __restrict__ col, int e) {
    int i = blockIdx.x * blockDim.x + threadIdx.x;
    if (i < e) atomicAdd(&g_deg[col[i]], 1);
}

__device__ __forceinline__ int block_excl_scan(int val, int* total) {
    __shared__ int wsum[32];
    int lane = threadIdx.x & 31, wid = threadIdx.x >> 5;
    int v = val;
#pragma unroll
    for (int o = 1; o < 32; o <<= 1) {
        int t = __shfl_up_sync(0xffffffffu, v, o);
        if (lane >= o) v += t;
    }
    if (lane == 31) wsum[wid] = v;
    __syncthreads();
    if (wid == 0) {
        int w = (lane < (blockDim.x >> 5)) ? wsum[lane] : 0;
#pragma unroll
        for (int o = 1; o < 32; o <<= 1) {
            int t = __shfl_up_sync(0xffffffffu, w, o);
            if (lane >= o) w += t;
        }
        wsum[lane] = w;
    }
    __syncthreads();
    int excl = v - val + (wid > 0 ? wsum[wid - 1] : 0);
    *total = wsum[(blockDim.x >> 5) - 1];
    return excl;
}

__global__ void scan1_kernel(int n) {
    int i = blockIdx.x * SCAN_B + threadIdx.x;
    int v = (i < n) ? g_deg[i] : 0;
    if (i < n) g_dinv[i] = rsqrtf((float)(v + 1));  // +1 self-loop
    int total;
    int excl = block_excl_scan(v, &total);
    if (i <= n) g_rowptr[i] = excl;
    if (threadIdx.x == 0) g_bsum[blockIdx.x] = total;
}

__global__ void scan2_kernel(int nb) {
    int v = (threadIdx.x < nb) ? g_bsum[threadIdx.x] : 0;
    int total;
    int excl = block_excl_scan(v, &total);
    if (threadIdx.x < nb) g_boff[threadIdx.x] = excl;
    if (threadIdx.x == 0) g_boff[nb] = total;
}

__global__ void scan3_kernel(int n, int nb) {
    int i = blockIdx.x * SCAN_B + threadIdx.x;
    if (i < n) g_rowptr[i] += g_boff[blockIdx.x];
    if (i == 0) g_rowptr[n] = g_boff[nb];
}

__global__ void fill_csr_kernel(const int* __restrict__ row,
                                const int* __restrict__ col, int e) {
    int i = blockIdx.x * blockDim.x + threadIdx.x;
    if (i < e) {
        int c = col[i];
        int p = g_rowptr[c] + atomicAdd(&g_fill[c], 1);
        g_csr_src[p] = row[i];
    }
}

// ---------------- GEMM v8: persistent, pipelined bf16x2 mma ----------------
// Grid = #SMs, block 1024 thr (32 warps = 8m x 4n), tile M=128 N=128 K=128.
// k-words interleaved (wpos) so fragment pairs (kw, kw+4) are adjacent -> LDS.64.
// A: double-buffered (hi,lo) planes, next tile prefetched via LDG during mainloop.
// B: staged once per layer, n-major [128 ncol][70 words].
// 3 passes: D += Ahi*Bhi + Ahi*Blo + Alo*Bhi (pass-major order, no RAW stalls).

#define A_STR 68
#define B_STR 70
#define A_PLANE (128 * A_STR)          // 8704 words
#define B_PLANE (128 * B_STR)          // 8960 words
#define GEMM_SMEM ((4 * A_PLANE + 2 * B_PLANE) * 4)  // 210944 B

__device__ __forceinline__ void mma_bf16(float* c, const uint32_t* a,
                                         uint32_t b0, uint32_t b1) {
    asm volatile(
        "mma.sync.aligned.m16n8k16.row.col.f32.bf16.bf16.f32 "
        "{%0,%1,%2,%3}, {%4,%5,%6,%7}, {%8,%9}, {%0,%1,%2,%3};"
        : "+f"(c[0]), "+f"(c[1]), "+f"(c[2]), "+f"(c[3])
        : "r"(a[0]), "r"(a[1]), "r"(a[2]), "r"(a[3]), "r"(b0), "r"(b1));
}

__device__ __forceinline__ uint32_t pack2(float x, float y) {
    __nv_bfloat162 h = make_bfloat162(__float2bfloat16(x), __float2bfloat16(y));
    return *(uint32_t*)&h;
}

// interleave within each 8-word group: j<4 -> 2j ; j>=4 -> 2(j-4)+1
__device__ __forceinline__ int wpos(int kw) {
    return (kw & 0x38) | ((kw & 3) << 1) | ((kw >> 2) & 1);
}

__device__ __forceinline__ void cvt_store_a(uint32_t* hi, uint32_t* lo,
                                            float4 v, int r, int c4) {
    float hx = __bfloat162float(__float2bfloat16(v.x));
    float hy = __bfloat162float(__float2bfloat16(v.y));
    float hz = __bfloat162float(__float2bfloat16(v.z));
    float hw = __bfloat162float(__float2bfloat16(v.w));
    int p0 = r * A_STR + wpos(2 * c4);
    int p1 = r * A_STR + wpos(2 * c4 + 1);
    hi[p0] = pack2(v.x, v.y);
    hi[p1] = pack2(v.z, v.w);
    lo[p0] = pack2(v.x - hx, v.y - hy);
    lo[p1] = pack2(v.z - hz, v.w - hw);
}

__global__ __launch_bounds__(1024, 1)
void gemm_mma(const float* __restrict__ X, const float* __restrict__ W,
              int n, int numTiles) {
    extern __shared__ uint32_t smem[];
    uint32_t* sBhi = smem + 4 * A_PLANE;
    uint32_t* sBlo = sBhi + B_PLANE;

    int tid  = threadIdx.x;
    int lane = tid & 31;
    int w    = tid >> 5;
    int wm   = w & 7;   // 8 m-slabs of 16 rows
    int wn   = w >> 3;  // 4 n-quarters of 32 cols
    int g    = lane >> 2;
    int q    = lane & 3;

    // ---- stage W once: n-major [ncol][B_STR], k-words interleaved ----
    for (int i = tid; i < 64 * 128; i += 1024) {
        int kw = i >> 7, nn = i & 127;
        float v0 = W[(size_t)(2 * kw) * DD + nn];
        float v1 = W[(size_t)(2 * kw + 1) * DD + nn];
        float h0 = __bfloat162float(__float2bfloat16(v0));
        float h1 = __bfloat162float(__float2bfloat16(v1));
        int p = nn * B_STR + wpos(kw);
        sBhi[p] = pack2(v0, v1);
        sBlo[p] = pack2(v0 - h0, v1 - h1);
    }

    // ---- stage A for first tile into buffer 0 ----
    {
        int rowBase = blockIdx.x * 128;
        for (int i = tid; i < 128 * 32; i += 1024) {
            int r = i >> 5, c4 = i & 31;
            float4 v = make_float4(0.f, 0.f, 0.f, 0.f);
            if (rowBase + r < n)
                v = __ldg(&((const float4*)X)[(size_t)(rowBase + r) * 32 + c4]);
            cvt_store_a(smem, smem + A_PLANE, v, r, c4);
        }
    }
    __syncthreads();

    int cur = 0;
    for (int t = blockIdx.x; t < numTiles; t += gridDim.x) {
        int tn = t + gridDim.x;
        bool hasNext = tn < numTiles;

        // ---- prefetch next A tile into registers (hidden under mainloop) ----
        float4 pv[4];
        if (hasNext) {
#pragma unroll
            for (int j = 0; j < 4; ++j) {
                int idx = tid + j * 1024;
                int r = idx >> 5, c4 = idx & 31;
                int row = tn * 128 + r;
                pv[j] = (row < n)
                            ? __ldg(&((const float4*)X)[(size_t)row * 32 + c4])
                            : make_float4(0.f, 0.f, 0.f, 0.f);
            }
        }

        const uint32_t* Ahi = smem + (cur ? 2 * A_PLANE : 0);
        const uint32_t* Alo = Ahi + A_PLANE;

        // ---- mainloop ----
        float c[4][4];
#pragma unroll
        for (int nt = 0; nt < 4; ++nt)
#pragma unroll
            for (int j = 0; j < 4; ++j) c[nt][j] = 0.f;

        int m0 = wm * 16 + g;

#pragma unroll
        for (int ks = 0; ks < 8; ++ks) {
            int base = ks * 8 + 2 * q;

            uint2 h01 = *(const uint2*)&Ahi[m0 * A_STR + base];
            uint2 h23 = *(const uint2*)&Ahi[(m0 + 8) * A_STR + base];
            uint2 l01 = *(const uint2*)&Alo[m0 * A_STR + base];
            uint2 l23 = *(const uint2*)&Alo[(m0 + 8) * A_STR + base];
            uint32_t ahi[4] = {h01.x, h23.x, h01.y, h23.y};
            uint32_t alo[4] = {l01.x, l23.x, l01.y, l23.y};

            uint2 bh[4], bl[4];
#pragma unroll
            for (int nt = 0; nt < 4; ++nt) {
                int ncol = wn * 32 + nt * 8 + g;
                bh[nt] = *(const uint2*)&sBhi[ncol * B_STR + base];
                bl[nt] = *(const uint2*)&sBlo[ncol * B_STR + base];
            }
            // pass-major: consecutive MMAs hit different accumulators
#pragma unroll
            for (int nt = 0; nt < 4; ++nt) mma_bf16(c[nt], ahi, bh[nt].x, bh[nt].y);
#pragma unroll
            for (int nt = 0; nt < 4; ++nt) mma_bf16(c[nt], ahi, bl[nt].x, bl[nt].y);
#pragma unroll
            for (int nt = 0; nt < 4; ++nt) mma_bf16(c[nt], alo, bh[nt].x, bh[nt].y);
        }

        // ---- store prefetched tile into the other A buffer ----
        if (hasNext) {
            uint32_t* Nhi = smem + (cur ? 0 : 2 * A_PLANE);
            uint32_t* Nlo = Nhi + A_PLANE;
#pragma unroll
            for (int j = 0; j < 4; ++j) {
                int idx = tid + j * 1024;
                cvt_store_a(Nhi, Nlo, pv[j], idx >> 5, idx & 31);
            }
        }

        // ---- epilogue: scale by dinv[row], store float2 pairs ----
        int r0 = t * 128 + m0;
        int r1 = r0 + 8;
        float d0 = (r0 < n) ? g_dinv[r0] : 0.f;
        float d1 = (r1 < n) ? g_dinv[r1] : 0.f;
#pragma unroll
        for (int nt = 0; nt < 4; ++nt) {
            int col = wn * 32 + nt * 8 + 2 * q;
            if (r0 < n)
                *(float2*)(g_h + (size_t)r0 * DD + col) =
                    make_float2(c[nt][0] * d0, c[nt][1] * d0);
            if (r1 < n)
                *(float2*)(g_h + (size_t)r1 * DD + col) =
                    make_float2(c[nt][2] * d1, c[nt][3] * d1);
        }

        __syncthreads();
        cur ^= 1;
    }
}

// ---------------- Aggregation: gather, no atomics ----------------
__global__ void aggregate_kernel(const float* __restrict__ bias,
                                 float* __restrict__ out, int n) {
    int node = (blockIdx.x * blockDim.x + threadIdx.x) >> 5;
    int lane = threadIdx.x & 31;
    if (node >= n) return;

    const float4* H = (const float4*)g_h;
    float4 acc = __ldg(&H[(size_t)node * 32 + lane]);  // self-loop h'

    int p   = g_rowptr[node];
    int end = g_rowptr[node + 1];
    for (; p + 4 <= end; p += 4) {
        int s0 = __ldg(&g_csr_src[p + 0]);
        int s1 = __ldg(&g_csr_src[p + 1]);
        int s2 = __ldg(&g_csr_src[p + 2]);
        int s3 = __ldg(&g_csr_src[p + 3]);
        float4 v0 = __ldg(&H[(size_t)s0 * 32 + lane]);
        float4 v1 = __ldg(&H[(size_t)s1 * 32 + lane]);
        float4 v2 = __ldg(&H[(size_t)s2 * 32 + lane]);
        float4 v3 = __ldg(&H[(size_t)s3 * 32 + lane]);
        acc.x += (v0.x + v1.x) + (v2.x + v3.x);
        acc.y += (v0.y + v1.y) + (v2.y + v3.y);
        acc.z += (v0.z + v1.z) + (v2.z + v3.z);
        acc.w += (v0.w + v1.w) + (v2.w + v3.w);
    }
    for (; p < end; ++p) {
        int s = __ldg(&g_csr_src[p]);
        float4 v = __ldg(&H[(size_t)s * 32 + lane]);
        acc.x += v.x; acc.y += v.y; acc.z += v.z; acc.w += v.w;
    }

    float di  = g_dinv[node];
    float4 bb = __ldg(&((const float4*)bias)[lane]);
    float4 o;
    o.x = fmaxf(acc.x * di + bb.x, 0.f);
    o.y = fmaxf(acc.y * di + bb.y, 0.f);
    o.z = fmaxf(acc.z * di + bb.z, 0.f);
    o.w = fmaxf(acc.w * di + bb.w, 0.f);
    ((float4*)out)[(size_t)node * 32 + lane] = o;
}

extern "C" void kernel_launch(void* const* d_in, const int* in_sizes, int n_in,
                              void* d_out, int out_size) {
    const float* x  = (const float*)d_in[0];
    const int*   ei = (const int*)d_in[1];
    const float* W  = (const float*)d_in[4];
    const float* b  = (const float*)d_in[5];
    float* out = (float*)d_out;

    int n = in_sizes[0] / DD;      // 50000
    int e = in_sizes[1] / 2;       // 800000
    const int* rowp = ei;          // sources
    const int* colp = ei + e;      // destinations
    int nb = (n + SCAN_B - 1) / SCAN_B;
    int numTiles = (n + 127) / 128;

    int sms = 148;
    cudaDeviceGetAttribute(&sms, cudaDevAttrMultiProcessorCount, 0);
    int gemmGrid = numTiles < sms ? numTiles : sms;

    cudaFuncSetAttribute(gemm_mma,
                         cudaFuncAttributeMaxDynamicSharedMemorySize, GEMM_SMEM);

    float* bufp = nullptr;
    cudaGetSymbolAddress((void**)&bufp, g_buf);

    // Preprocess; layer-0 GEMM only needs dinv (scan1), so the CSR build
    // continues behind it.
    zero_counters_kernel<<<(n + 255) / 256, 256>>>(n);
    count_deg_kernel<<<(e + 255) / 256, 256>>>(colp, e);
    scan1_kernel<<<nb, SCAN_B>>>(n);
    gemm_mma<<<gemmGrid, 1024, GEMM_SMEM>>>(x, W, n, numTiles);  // layer 0
    scan2_kernel<<<1, SCAN_B>>>(nb);
    scan3_kernel<<<nb, SCAN_B>>>(n, nb);
    fill_csr_kernel<<<(e + 255) / 256, 256>>>(rowp, colp, e);
    aggregate_kernel<<<(n * 32 + 255) / 256, 256>>>(b, bufp, n);  // layer 0 agg

    const float* X = bufp;
    for (int l = 1; l < LL; ++l) {
        gemm_mma<<<gemmGrid, 1024, GEMM_SMEM>>>(X, W + (size_t)l * DD * DD, n,
                                                numTiles);
        aggregate_kernel<<<(n * 32 + 255) / 256, 256>>>(
            b + (size_t)l * DD, (l == LL - 1) ? out : bufp, n);
        X = bufp;
    }
}

// round 11
// speedup vs baseline: 1.1537x; 1.1537x over previous
#include <cuda_runtime.h>
#include <cuda_bf16.h>
#include <cstdint>

#define MAXN 50000
#define DD 128
#define MAXE 800000
#define LL 4
#define SCAN_B 1024

// Scratch (no allocations allowed)
__device__ int    g_deg[MAXN];
__device__ int    g_fill[MAXN];
__device__ int    g_rowptr[MAXN + 1];
__device__ int    g_bsum[64];
__device__ int    g_boff[64];
__device__ int    g_csr_src[MAXE];
__device__ float  g_dinv[MAXN];
__device__ float  g_h[(size_t)MAXN * DD];    // h' = (X@W)*dinv[row]
__device__ float  g_buf[(size_t)MAXN * DD];  // layer output ping buffer

// ---------------- preprocessing ----------------

__global__ void zero_counters_kernel(int n) {
    int i = blockIdx.x * blockDim.x + threadIdx.x;
    if (i < n) { g_deg[i] = 0; g_fill[i] = 0; }
}

__global__ void count_deg_kernel(const int* __restrict__ col, int e) {
    int i = blockIdx.x * blockDim.x + threadIdx.x;
    if (i < e) atomicAdd(&g_deg[col[i]], 1);
}

__device__ __forceinline__ int block_excl_scan(int val, int* total) {
    __shared__ int wsum[32];
    int lane = threadIdx.x & 31, wid = threadIdx.x >> 5;
    int v = val;
#pragma unroll
    for (int o = 1; o < 32; o <<= 1) {
        int t = __shfl_up_sync(0xffffffffu, v, o);
        if (lane >= o) v += t;
    }
    if (lane == 31) wsum[wid] = v;
    __syncthreads();
    if (wid == 0) {
        int w = (lane < (blockDim.x >> 5)) ? wsum[lane] : 0;
#pragma unroll
        for (int o = 1; o < 32; o <<= 1) {
            int t = __shfl_up_sync(0xffffffffu, w, o);
            if (lane >= o) w += t;
        }
        wsum[lane] = w;
    }
    __syncthreads();
    int excl = v - val + (wid > 0 ? wsum[wid - 1] : 0);
    *total = wsum[(blockDim.x >> 5) - 1];
    return excl;
}

__global__ void scan1_kernel(int n) {
    int i = blockIdx.x * SCAN_B + threadIdx.x;
    int v = (i < n) ? g_deg[i] : 0;
    if (i < n) g_dinv[i] = rsqrtf((float)(v + 1));  // +1 self-loop
    int total;
    int excl = block_excl_scan(v, &total);
    if (i <= n) g_rowptr[i] = excl;
    if (threadIdx.x == 0) g_bsum[blockIdx.x] = total;
}

__global__ void scan2_kernel(int nb) {
    int v = (threadIdx.x < nb) ? g_bsum[threadIdx.x] : 0;
    int total;
    int excl = block_excl_scan(v, &total);
    if (threadIdx.x < nb) g_boff[threadIdx.x] = excl;
    if (threadIdx.x == 0) g_boff[nb] = total;
}

__global__ void scan3_kernel(int n, int nb) {
    int i = blockIdx.x * SCAN_B + threadIdx.x;
    if (i < n) g_rowptr[i] += g_boff[blockIdx.x];
    if (i == 0) g_rowptr[n] = g_boff[nb];
}

__global__ void fill_csr_kernel(const int* __restrict__ row,
                                const int* __restrict__ col, int e) {
    int i = blockIdx.x * blockDim.x + threadIdx.x;
    if (i < e) {
        int c = col[i];
        int p = g_rowptr[c] + atomicAdd(&g_fill[c], 1);
        g_csr_src[p] = row[i];
    }
}

// ---------------- GEMM v9: persistent ldmatrix bf16x2 mma ----------------
// Grid = #SMs, block 1024 thr (32 warps = 8m x 4n), tile M=128 N=128 K=128.
// Planes [128 rows][68 words] (row = m for A, ncol for B; 64 k-words + pad).
// Mainloop per k16-step: 6 ldmatrix.x4 + 12 mma (pass-major).
// A: double-buffered, next tile prefetched to registers during mainloop.
// 3 passes: D += Ahi*Bhi + Ahi*Blo + Alo*Bhi.

#define PSTR 68
#define PLANE (128 * PSTR)                      // 8704 words
#define GEMM_SMEM (6 * PLANE * 4)               // 208896 B

__device__ __forceinline__ void mma_bf16(float* c, const uint32_t* a,
                                         uint32_t b0, uint32_t b1) {
    asm volatile(
        "mma.sync.aligned.m16n8k16.row.col.f32.bf16.bf16.f32 "
        "{%0,%1,%2,%3}, {%4,%5,%6,%7}, {%8,%9}, {%0,%1,%2,%3};"
        : "+f"(c[0]), "+f"(c[1]), "+f"(c[2]), "+f"(c[3])
        : "r"(a[0]), "r"(a[1]), "r"(a[2]), "r"(a[3]), "r"(b0), "r"(b1));
}

__device__ __forceinline__ void ldsm4(uint32_t* r, uint32_t addr) {
    asm volatile(
        "ldmatrix.sync.aligned.m8n8.x4.shared.b16 {%0,%1,%2,%3}, [%4];"
        : "=r"(r[0]), "=r"(r[1]), "=r"(r[2]), "=r"(r[3]) : "r"(addr));
}

__device__ __forceinline__ uint32_t pack2(float x, float y) {
    __nv_bfloat162 h = make_bfloat162(__float2bfloat16(x), __float2bfloat16(y));
    return *(uint32_t*)&h;
}

__device__ __forceinline__ void cvt_store_a(uint32_t* hi, uint32_t* lo,
                                            float4 v, int r, int c4) {
    float hx = __bfloat162float(__float2bfloat16(v.x));
    float hy = __bfloat162float(__float2bfloat16(v.y));
    float hz = __bfloat162float(__float2bfloat16(v.z));
    float hw = __bfloat162float(__float2bfloat16(v.w));
    int p = r * PSTR + 2 * c4;
    *(uint2*)&hi[p] = make_uint2(pack2(v.x, v.y), pack2(v.z, v.w));
    *(uint2*)&lo[p] = make_uint2(pack2(v.x - hx, v.y - hy),
                                 pack2(v.z - hz, v.w - hw));
}

__global__ __launch_bounds__(1024, 1)
void gemm_mma(const float* __restrict__ X, const float* __restrict__ W,
              int n, int numTiles) {
    extern __shared__ uint32_t smem[];
    uint32_t* sBhi = smem + 4 * PLANE;
    uint32_t* sBlo = sBhi + PLANE;

    int tid  = threadIdx.x;
    int lane = tid & 31;
    int w    = tid >> 5;
    int wm   = w & 7;   // 8 m-slabs of 16 rows
    int wn   = w >> 3;  // 4 n-quarters of 32 cols
    int g    = lane >> 2;
    int q    = lane & 3;

    // ---- stage W once: n-major rows [ncol][PSTR], word kw = k pair ----
    for (int i = tid; i < 64 * 128; i += 1024) {
        int kw = i >> 7, nn = i & 127;
        float v0 = W[(size_t)(2 * kw) * DD + nn];
        float v1 = W[(size_t)(2 * kw + 1) * DD + nn];
        float h0 = __bfloat162float(__float2bfloat16(v0));
        float h1 = __bfloat162float(__float2bfloat16(v1));
        int p = nn * PSTR + kw;
        sBhi[p] = pack2(v0, v1);
        sBlo[p] = pack2(v0 - h0, v1 - h1);
    }

    // ---- stage A for first tile into buffer 0 ----
    {
        int rowBase = blockIdx.x * 128;
        for (int i = tid; i < 128 * 32; i += 1024) {
            int r = i >> 5, c4 = i & 31;
            float4 v = make_float4(0.f, 0.f, 0.f, 0.f);
            if (rowBase + r < n)
                v = __ldg(&((const float4*)X)[(size_t)(rowBase + r) * 32 + c4]);
            cvt_store_a(smem, smem + PLANE, v, r, c4);
        }
    }
    __syncthreads();

    // ---- per-lane ldmatrix byte offsets (within a plane) ----
    // A: row = wm*16 + (lane&15), kchunk = (lane>>4)*4 words (+ks*8 per step)
    uint32_t aOff = ((uint32_t)(wm * 16 + (lane & 15)) * PSTR +
                     (uint32_t)((lane >> 4) * 4)) * 4u;
    // B: row(ncol) = wn*32 + ntBase*8 + (lane&7) + (lane>>4)*8,
    //    kchunk = ((lane>>3)&1)*4 words (+ks*8 per step); ntBase in {0,2}
    uint32_t bRow0 = (uint32_t)(wn * 32 + (lane & 7) + ((lane >> 4) & 1) * 8);
    uint32_t bKch  = (uint32_t)(((lane >> 3) & 1) * 4);
    uint32_t bOff0 = (bRow0 * PSTR + bKch) * 4u;        // ntBase = 0
    uint32_t bOff1 = ((bRow0 + 16) * PSTR + bKch) * 4u; // ntBase = 2

    uint32_t sBhiA = (uint32_t)__cvta_generic_to_shared(sBhi);
    uint32_t sBloA = (uint32_t)__cvta_generic_to_shared(sBlo);

    int cur = 0;
    for (int t = blockIdx.x; t < numTiles; t += gridDim.x) {
        int tn = t + gridDim.x;
        bool hasNext = tn < numTiles;

        // ---- prefetch next A tile into registers ----
        float4 pv[4];
        if (hasNext) {
#pragma unroll
            for (int j = 0; j < 4; ++j) {
                int idx = tid + j * 1024;
                int r = idx >> 5, c4 = idx & 31;
                int row = tn * 128 + r;
                pv[j] = (row < n)
                            ? __ldg(&((const float4*)X)[(size_t)row * 32 + c4])
                            : make_float4(0.f, 0.f, 0.f, 0.f);
            }
        }

        uint32_t aHiA = (uint32_t)__cvta_generic_to_shared(
                            smem + (cur ? 2 * PLANE : 0)) + aOff;
        uint32_t aLoA = aHiA + PLANE * 4;

        // ---- mainloop: 8 k16-steps, 6 ldmatrix + 12 mma each ----
        float c[4][4];
#pragma unroll
        for (int nt = 0; nt < 4; ++nt)
#pragma unroll
            for (int j = 0; j < 4; ++j) c[nt][j] = 0.f;

#pragma unroll
        for (int ks = 0; ks < 8; ++ks) {
            uint32_t kb = (uint32_t)(ks * 32);  // 8 words per step

            uint32_t ahi[4], alo[4];
            ldsm4(ahi, aHiA + kb);
            ldsm4(alo, aLoA + kb);

            uint32_t bh[8], bl[8];  // [nt0 b0,b1, nt1 b0,b1] x2 ntBases
            ldsm4(bh + 0, sBhiA + bOff0 + kb);
            ldsm4(bh + 4, sBhiA + bOff1 + kb);
            ldsm4(bl + 0, sBloA + bOff0 + kb);
            ldsm4(bl + 4, sBloA + bOff1 + kb);

            // pass-major: consecutive MMAs hit different accumulators
#pragma unroll
            for (int nt = 0; nt < 4; ++nt)
                mma_bf16(c[nt], ahi, bh[2 * nt], bh[2 * nt + 1]);
#pragma unroll
            for (int nt = 0; nt < 4; ++nt)
                mma_bf16(c[nt], ahi, bl[2 * nt], bl[2 * nt + 1]);
#pragma unroll
            for (int nt = 0; nt < 4; ++nt)
                mma_bf16(c[nt], alo, bh[2 * nt], bh[2 * nt + 1]);
        }

        // ---- store prefetched tile into the other A buffer ----
        if (hasNext) {
            uint32_t* Nhi = smem + (cur ? 0 : 2 * PLANE);
            uint32_t* Nlo = Nhi + PLANE;
#pragma unroll
            for (int j = 0; j < 4; ++j) {
                int idx = tid + j * 1024;
                cvt_store_a(Nhi, Nlo, pv[j], idx >> 5, idx & 31);
            }
        }

        // ---- epilogue: scale by dinv[row], store float2 pairs ----
        int m0 = wm * 16 + g;
        int r0 = t * 128 + m0;
        int r1 = r0 + 8;
        float d0 = (r0 < n) ? g_dinv[r0] : 0.f;
        float d1 = (r1 < n) ? g_dinv[r1] : 0.f;
#pragma unroll
        for (int nt = 0; nt < 4; ++nt) {
            int col = wn * 32 + nt * 8 + 2 * q;
            if (r0 < n)
                *(float2*)(g_h + (size_t)r0 * DD + col) =
                    make_float2(c[nt][0] * d0, c[nt][1] * d0);
            if (r1 < n)
                *(float2*)(g_h + (size_t)r1 * DD + col) =
                    make_float2(c[nt][2] * d1, c[nt][3] * d1);
        }

        __syncthreads();
        cur ^= 1;
    }
}

// ---------------- Aggregation: gather, no atomics ----------------
__global__ void aggregate_kernel(const float* __restrict__ bias,
                                 float* __restrict__ out, int n) {
    int node = (blockIdx.x * blockDim.x + threadIdx.x) >> 5;
    int lane = threadIdx.x & 31;
    if (node >= n) return;

    const float4* H = (const float4*)g_h;
    float4 acc = __ldg(&H[(size_t)node * 32 + lane]);  // self-loop h'

    int p   = g_rowptr[node];
    int end = g_rowptr[node + 1];
    for (; p + 4 <= end; p += 4) {
        int s0 = __ldg(&g_csr_src[p + 0]);
        int s1 = __ldg(&g_csr_src[p + 1]);
        int s2 = __ldg(&g_csr_src[p + 2]);
        int s3 = __ldg(&g_csr_src[p + 3]);
        float4 v0 = __ldg(&H[(size_t)s0 * 32 + lane]);
        float4 v1 = __ldg(&H[(size_t)s1 * 32 + lane]);
        float4 v2 = __ldg(&H[(size_t)s2 * 32 + lane]);
        float4 v3 = __ldg(&H[(size_t)s3 * 32 + lane]);
        acc.x += (v0.x + v1.x) + (v2.x + v3.x);
        acc.y += (v0.y + v1.y) + (v2.y + v3.y);
        acc.z += (v0.z + v1.z) + (v2.z + v3.z);
        acc.w += (v0.w + v1.w) + (v2.w + v3.w);
    }
    for (; p < end; ++p) {
        int s = __ldg(&g_csr_src[p]);
        float4 v = __ldg(&H[(size_t)s * 32 + lane]);
        acc.x += v.x; acc.y += v.y; acc.z += v.z; acc.w += v.w;
    }

    float di  = g_dinv[node];
    float4 bb = __ldg(&((const float4*)bias)[lane]);
    float4 o;
    o.x = fmaxf(acc.x * di + bb.x, 0.f);
    o.y = fmaxf(acc.y * di + bb.y, 0.f);
    o.z = fmaxf(acc.z * di + bb.z, 0.f);
    o.w = fmaxf(acc.w * di + bb.w, 0.f);
    ((float4*)out)[(size_t)node * 32 + lane] = o;
}

extern "C" void kernel_launch(void* const* d_in, const int* in_sizes, int n_in,
                              void* d_out, int out_size) {
    const float* x  = (const float*)d_in[0];
    const int*   ei = (const int*)d_in[1];
    const float* W  = (const float*)d_in[4];
    const float* b  = (const float*)d_in[5];
    float* out = (float*)d_out;

    int n = in_sizes[0] / DD;      // 50000
    int e = in_sizes[1] / 2;       // 800000
    const int* rowp = ei;          // sources
    const int* colp = ei + e;      // destinations
    int nb = (n + SCAN_B - 1) / SCAN_B;
    int numTiles = (n + 127) / 128;

    int sms = 148;
    cudaDeviceGetAttribute(&sms, cudaDevAttrMultiProcessorCount, 0);
    int gemmGrid = numTiles < sms ? numTiles : sms;

    cudaFuncSetAttribute(gemm_mma,
                         cudaFuncAttributeMaxDynamicSharedMemorySize, GEMM_SMEM);

    float* bufp = nullptr;
    cudaGetSymbolAddress((void**)&bufp, g_buf);

    // Preprocess; layer-0 GEMM only needs dinv (scan1), so the CSR build
    // continues behind it.
    zero_counters_kernel<<<(n + 255) / 256, 256>>>(n);
    count_deg_kernel<<<(e + 255) / 256, 256>>>(colp, e);
    scan1_kernel<<<nb, SCAN_B>>>(n);
    gemm_mma<<<gemmGrid, 1024, GEMM_SMEM>>>(x, W, n, numTiles);  // layer 0
    scan2_kernel<<<1, SCAN_B>>>(nb);
    scan3_kernel<<<nb, SCAN_B>>>(n, nb);
    fill_csr_kernel<<<(e + 255) / 256, 256>>>(rowp, colp, e);
    aggregate_kernel<<<(n * 32 + 255) / 256, 256>>>(b, bufp, n);  // layer 0 agg

    const float* X = bufp;
    for (int l = 1; l < LL; ++l) {
        gemm_mma<<<gemmGrid, 1024, GEMM_SMEM>>>(X, W + (size_t)l * DD * DD, n,
                                                numTiles);
        aggregate_kernel<<<(n * 32 + 255) / 256, 256>>>(
            b + (size_t)l * DD, (l == LL - 1) ? out : bufp, n);
        X = bufp;
    }
}